// round 6
// baseline (speedup 1.0000x reference)
#include <cuda_runtime.h>
#include <cuda_fp16.h>
#include <cstdint>
#include <math.h>

// Problem dims (fixed by reference)
#define BATCH 4
#define SEQ   4096
#define DIM   1024
#define HEADS 16
#define HDIM  64            // DIM / HEADS
#define ROWS  (BATCH*SEQ)   // 16384
#define N_QKV (3*DIM)       // 3072
#define NCHUNK 8            // context split factor

// ---------------- scratch (device globals; no allocations allowed) ------------
__device__ float  g_qkv     [(size_t)ROWS * N_QKV];                // fp32 qkv
__device__ float  g_ctx     [(size_t)BATCH*HEADS*HDIM*HDIM];
__device__ float  g_ctxpart [(size_t)BATCH*HEADS*NCHUNK*HDIM*HDIM];
__device__ float  g_csumpart[(size_t)BATCH*HEADS*NCHUNK*HDIM];
// pre-split fp16 operands (big + small = exact-ish fp32)
__device__ __half g_xb   [(size_t)ROWS * DIM];     // x big     [M][K]
__device__ __half g_xs   [(size_t)ROWS * DIM];     // x small
__device__ __half g_wqkvb[(size_t)N_QKV * DIM];    // W_qkv^T big  [N][K]
__device__ __half g_wqkvs[(size_t)N_QKV * DIM];
__device__ __half g_wprjb[(size_t)DIM * DIM];      // W_proj^T big [N][K]
__device__ __half g_wprjs[(size_t)DIM * DIM];
__device__ __half g_attnb[(size_t)ROWS * DIM];     // attn big  [M][K]
__device__ __half g_attns[(size_t)ROWS * DIM];

// ---------------- helpers ----------------------------------------------------
__device__ __forceinline__ void mma_f16(float& c0, float& c1, float& c2, float& c3,
                                        uint32_t a0, uint32_t a1, uint32_t a2, uint32_t a3,
                                        uint32_t b0, uint32_t b1) {
    asm volatile(
        "mma.sync.aligned.m16n8k16.row.col.f32.f16.f16.f32 "
        "{%0,%1,%2,%3}, {%4,%5,%6,%7}, {%8,%9}, {%0,%1,%2,%3};\n"
        : "+f"(c0), "+f"(c1), "+f"(c2), "+f"(c3)
        : "r"(a0), "r"(a1), "r"(a2), "r"(a3), "r"(b0), "r"(b1));
}

__device__ __forceinline__ void cp_async16(uint32_t smem_addr, const void* gptr) {
    asm volatile("cp.async.cg.shared.global [%0], [%1], 16;\n"
                 :: "r"(smem_addr), "l"(gptr));
}
__device__ __forceinline__ void cp_commit() {
    asm volatile("cp.async.commit_group;\n" ::: "memory");
}
template <int N>
__device__ __forceinline__ void cp_wait() {
    asm volatile("cp.async.wait_group %0;\n" :: "n"(N) : "memory");
}

__device__ __forceinline__ float2 ffma2(float2 a, float2 b, float2 c) {
    uint64_t au, bu, cu, du;
    au = *reinterpret_cast<uint64_t*>(&a);
    bu = *reinterpret_cast<uint64_t*>(&b);
    cu = *reinterpret_cast<uint64_t*>(&c);
    asm("fma.rn.f32x2 %0, %1, %2, %3;" : "=l"(du) : "l"(au), "l"(bu), "l"(cu));
    return *reinterpret_cast<float2*>(&du);
}

// split pair of fp32 -> big half2 + small half2 (packed uint32)
__device__ __forceinline__ void split2u(float x, float y, uint32_t& big, uint32_t& sml) {
    __half2 hb = __floats2half2_rn(x, y);
    float2 back = __half22float2(hb);
    __half2 hs = __floats2half2_rn(x - back.x, y - back.y);
    big = *reinterpret_cast<uint32_t*>(&hb);
    sml = *reinterpret_cast<uint32_t*>(&hs);
}

// ---------------- prep: elementwise split of row-major fp32 -> half pairs -----
__global__ __launch_bounds__(256) void split_kernel(const float* __restrict__ src,
                                                    __half* __restrict__ ob,
                                                    __half* __restrict__ os)
{
    size_t t = (size_t)blockIdx.x * 256 + threadIdx.x;   // one float4 per thread
    float4 v = reinterpret_cast<const float4*>(src)[t];
    uint32_t b01, s01, b23, s23;
    split2u(v.x, v.y, b01, s01);
    split2u(v.z, v.w, b23, s23);
    uint2 ub = make_uint2(b01, b23);
    uint2 us = make_uint2(s01, s23);
    *reinterpret_cast<uint2*>(ob + 4 * t) = ub;
    *reinterpret_cast<uint2*>(os + 4 * t) = us;
}

// ---------------- prep: W [K][N] fp32 -> transposed [N][K] half pairs ---------
__global__ __launch_bounds__(256) void split_wt_kernel(const float* __restrict__ W,
                                                       __half* __restrict__ ob,
                                                       __half* __restrict__ os,
                                                       int K, int N)
{
    __shared__ float tile[32][33];
    const int n0 = blockIdx.x * 32;
    const int k0 = blockIdx.y * 32;
    const int tid = threadIdx.x;
    const int r  = tid >> 3;          // 0..31
    const int c4 = (tid & 7) * 4;     // 0..28

    float4 v = *reinterpret_cast<const float4*>(W + (size_t)(k0 + r) * N + n0 + c4);
    tile[r][c4] = v.x; tile[r][c4 + 1] = v.y; tile[r][c4 + 2] = v.z; tile[r][c4 + 3] = v.w;
    __syncthreads();

    // write transposed: thread -> n = r, k = c4..c4+3
    const int n = r;
    #pragma unroll
    for (int j = 0; j < 4; j++) {
        float f = tile[c4 + j][n];
        __half hb = __float2half_rn(f);
        __half hs = __float2half_rn(f - __half2float(hb));
        size_t o = (size_t)(n0 + n) * K + k0 + c4 + j;
        ob[o] = hb;
        os[o] = hs;
    }
}

// ---------------- big GEMM: C[M,N] = A[M,K] @ B^T[N,K] + bias  (3xFP16) -------
// A given as big/small half [M][K]; B given as big/small half [N][K] (pre-transposed).
// Block tile 128x128, BK=32, 8 warps 2(m)x4(n), warp tile 64x32, 2-stage cp.async.
#define ST_STRIDE 40                       // halfs per smem row (80B) -> conflict-free
#define ARR_HALFS (128 * ST_STRIDE)        // 5120 halfs per array
#define STAGE_HALFS (4 * ARR_HALFS)        // Ab, As, Bb, Bs
#define GEMM_SMEM_BYTES (2 * STAGE_HALFS * 2)   // 81920 B

__global__ __launch_bounds__(256) void gemm_f16x3_kernel(
    const __half* __restrict__ Ab, const __half* __restrict__ As,
    const __half* __restrict__ Bb, const __half* __restrict__ Bs,
    const float* __restrict__ bias, float* __restrict__ C,
    int M, int N, int K)
{
    extern __shared__ __half smem[];

    const int tid  = threadIdx.x;
    const int warp = tid >> 5;
    const int lane = tid & 31;
    const int gid  = lane >> 2;     // 0..7
    const int tig  = lane & 3;      // 0..3

    const int m0 = blockIdx.y * 128;
    const int n0 = blockIdx.x * 128;
    const int wm = (warp & 1) * 64;
    const int wn = (warp >> 1) * 32;

    // per-thread cp.async slots: 2 chunks per array; chunk f covers row f>>2, halfs (f&3)*8
    int rr[2], cc[2];
    #pragma unroll
    for (int i = 0; i < 2; i++) {
        int f = tid + i * 256;
        rr[i] = f >> 2;
        cc[i] = (f & 3) * 8;
    }

    const int ntiles = K >> 5;

    auto issue_tile = [&](int kt, int s) {
        __half* Sab = smem + (size_t)s * STAGE_HALFS;
        __half* Sas = Sab + ARR_HALFS;
        __half* Sbb = Sas + ARR_HALFS;
        __half* Sbs = Sbb + ARR_HALFS;
        #pragma unroll
        for (int i = 0; i < 2; i++) {
            int r = rr[i], c = cc[i];
            size_t goA = (size_t)(m0 + r) * K + kt + c;
            size_t goB = (size_t)(n0 + r) * K + kt + c;
            cp_async16((uint32_t)__cvta_generic_to_shared(Sab + r * ST_STRIDE + c), Ab + goA);
            cp_async16((uint32_t)__cvta_generic_to_shared(Sas + r * ST_STRIDE + c), As + goA);
            cp_async16((uint32_t)__cvta_generic_to_shared(Sbb + r * ST_STRIDE + c), Bb + goB);
            cp_async16((uint32_t)__cvta_generic_to_shared(Sbs + r * ST_STRIDE + c), Bs + goB);
        }
        cp_commit();
    };

    float acc[4][4][4];
    #pragma unroll
    for (int i = 0; i < 4; i++)
        #pragma unroll
        for (int j = 0; j < 4; j++)
            #pragma unroll
            for (int r = 0; r < 4; r++) acc[i][j][r] = 0.f;

    issue_tile(0, 0);

    for (int t = 0; t < ntiles; t++) {
        const int s = t & 1;
        if (t + 1 < ntiles) {
            issue_tile((t + 1) << 5, s ^ 1);
            cp_wait<1>();
        } else {
            cp_wait<0>();
        }
        __syncthreads();

        const __half* Sab = smem + (size_t)s * STAGE_HALFS;
        const __half* Sas = Sab + ARR_HALFS;
        const __half* Sbb = Sas + ARR_HALFS;
        const __half* Sbs = Sbb + ARR_HALFS;
        // uint32 views (all frag offsets are even halfs)
        const uint32_t* uab = reinterpret_cast<const uint32_t*>(Sab);
        const uint32_t* uas = reinterpret_cast<const uint32_t*>(Sas);
        const uint32_t* ubb = reinterpret_cast<const uint32_t*>(Sbb);
        const uint32_t* ubs = reinterpret_cast<const uint32_t*>(Sbs);

        #pragma unroll
        for (int kk = 0; kk < 32; kk += 16) {
            const int k0w = (kk + 2 * tig) >> 1;        // uint32 col index
            uint32_t ab[4][4], asml[4][4];
            #pragma unroll
            for (int mt = 0; mt < 4; mt++) {
                int rA = wm + mt * 16 + gid;
                int base0 = rA * (ST_STRIDE / 2) + k0w;
                int base1 = (rA + 8) * (ST_STRIDE / 2) + k0w;
                ab[mt][0] = uab[base0];     ab[mt][1] = uab[base1];
                ab[mt][2] = uab[base0 + 4]; ab[mt][3] = uab[base1 + 4];
                asml[mt][0] = uas[base0];     asml[mt][1] = uas[base1];
                asml[mt][2] = uas[base0 + 4]; asml[mt][3] = uas[base1 + 4];
            }
            uint32_t bb[4][2], bs[4][2];
            #pragma unroll
            for (int nt = 0; nt < 4; nt++) {
                int cB = wn + nt * 8 + gid;
                int base = cB * (ST_STRIDE / 2) + k0w;
                bb[nt][0] = ubb[base]; bb[nt][1] = ubb[base + 4];
                bs[nt][0] = ubs[base]; bs[nt][1] = ubs[base + 4];
            }
            #pragma unroll
            for (int mt = 0; mt < 4; mt++)
                #pragma unroll
                for (int nt = 0; nt < 4; nt++) {
                    mma_f16(acc[mt][nt][0], acc[mt][nt][1], acc[mt][nt][2], acc[mt][nt][3],
                            ab[mt][0], ab[mt][1], ab[mt][2], ab[mt][3],
                            bb[nt][0], bb[nt][1]);
                    mma_f16(acc[mt][nt][0], acc[mt][nt][1], acc[mt][nt][2], acc[mt][nt][3],
                            ab[mt][0], ab[mt][1], ab[mt][2], ab[mt][3],
                            bs[nt][0], bs[nt][1]);
                    mma_f16(acc[mt][nt][0], acc[mt][nt][1], acc[mt][nt][2], acc[mt][nt][3],
                            asml[mt][0], asml[mt][1], asml[mt][2], asml[mt][3],
                            bb[nt][0], bb[nt][1]);
                }
        }
        __syncthreads();
    }

    // ---- epilogue: + bias, store ----
    #pragma unroll
    for (int mt = 0; mt < 4; mt++) {
        int row = m0 + wm + mt * 16 + gid;
        #pragma unroll
        for (int nt = 0; nt < 4; nt++) {
            int col = n0 + wn + nt * 8 + tig * 2;
            float b0 = bias[col], b1 = bias[col + 1];
            C[(size_t)row * N + col]           = acc[mt][nt][0] + b0;
            C[(size_t)row * N + col + 1]       = acc[mt][nt][1] + b1;
            C[(size_t)(row + 8) * N + col]     = acc[mt][nt][2] + b0;
            C[(size_t)(row + 8) * N + col + 1] = acc[mt][nt][3] + b1;
        }
    }
}

// ---------------- context partial: per (b,h,chunk) ----------------------------
#define CK_STRIDE 68
#define CHUNK_ROWS (SEQ / NCHUNK)   // 512
__global__ __launch_bounds__(256) void context_partial_kernel()
{
    __shared__ float sk[64 * CK_STRIDE];
    __shared__ float sv[64 * CK_STRIDE];

    const int bid = blockIdx.x;
    const int bh  = bid >> 3;
    const int c   = bid & 7;
    const int b   = bh >> 4;
    const int h   = bh & 15;
    const int tid = threadIdx.x;
    const int ty  = tid >> 4;
    const int tx  = tid & 15;
    const int d0  = ty * 4;
    const int e0  = tx * 4;

    const float* kbase = g_qkv + (size_t)b * SEQ * N_QKV + DIM     + h * HDIM;
    const float* vbase = g_qkv + (size_t)b * SEQ * N_QKV + 2 * DIM + h * HDIM;

    float2 acc2[4][2];
    #pragma unroll
    for (int i = 0; i < 4; i++) {
        acc2[i][0] = make_float2(0.f, 0.f);
        acc2[i][1] = make_float2(0.f, 0.f);
    }
    float csum = 0.f;

    const int nlo = c * CHUNK_ROWS;
    for (int n0 = nlo; n0 < nlo + CHUNK_ROWS; n0 += 64) {
        #pragma unroll
        for (int i = 0; i < 4; i++) {
            int f  = tid + i * 256;
            int r  = f >> 4;
            int c4 = (f & 15) * 4;
            size_t go = (size_t)(n0 + r) * N_QKV + c4;
            float4 kv = *reinterpret_cast<const float4*>(kbase + go);
            float* dk = &sk[r * CK_STRIDE + c4];
            dk[0] = expf(kv.x); dk[1] = expf(kv.y); dk[2] = expf(kv.z); dk[3] = expf(kv.w);
            float4 vv = *reinterpret_cast<const float4*>(vbase + go);
            *reinterpret_cast<float4*>(&sv[r * CK_STRIDE + c4]) = vv;
        }
        __syncthreads();

        if (tid < 64) {
            #pragma unroll 8
            for (int r = 0; r < 64; r++) csum += sk[r * CK_STRIDE + tid];
        }
        #pragma unroll 4
        for (int r = 0; r < 64; r++) {
            float4 kf = *reinterpret_cast<const float4*>(&sk[r * CK_STRIDE + d0]);
            float4 vf = *reinterpret_cast<const float4*>(&sv[r * CK_STRIDE + e0]);
            float2 v0 = make_float2(vf.x, vf.y);
            float2 v1 = make_float2(vf.z, vf.w);
            float ka[4] = {kf.x, kf.y, kf.z, kf.w};
            #pragma unroll
            for (int i = 0; i < 4; i++) {
                float2 kd = make_float2(ka[i], ka[i]);
                acc2[i][0] = ffma2(kd, v0, acc2[i][0]);
                acc2[i][1] = ffma2(kd, v1, acc2[i][1]);
            }
        }
        __syncthreads();
    }

    float* part = g_ctxpart + (size_t)bid * HDIM * HDIM;
    #pragma unroll
    for (int i = 0; i < 4; i++) {
        part[(d0 + i) * HDIM + e0    ] = acc2[i][0].x;
        part[(d0 + i) * HDIM + e0 + 1] = acc2[i][0].y;
        part[(d0 + i) * HDIM + e0 + 2] = acc2[i][1].x;
        part[(d0 + i) * HDIM + e0 + 3] = acc2[i][1].y;
    }
    if (tid < 64) g_csumpart[(size_t)bid * HDIM + tid] = csum;
}

// ---------------- reduce partials -> normalized ctx ---------------------------
__global__ __launch_bounds__(256) void reduce_ctx_kernel()
{
    __shared__ float sinv[64];
    const int bh  = blockIdx.x;
    const int tid = threadIdx.x;

    if (tid < 64) {
        float s = 0.f;
        #pragma unroll
        for (int c = 0; c < NCHUNK; c++)
            s += g_csumpart[(size_t)(bh * NCHUNK + c) * HDIM + tid];
        sinv[tid] = 1.0f / s;
    }
    __syncthreads();

    for (int idx = tid; idx < HDIM * HDIM; idx += 256) {
        float s = 0.f;
        #pragma unroll
        for (int c = 0; c < NCHUNK; c++)
            s += g_ctxpart[(size_t)(bh * NCHUNK + c) * HDIM * HDIM + idx];
        g_ctx[(size_t)bh * HDIM * HDIM + idx] = s * sinv[idx >> 6];
    }
}

// ---------------- q-softmax + q @ ctx, fused fp16-split store -----------------
__global__ __launch_bounds__(256) void qctx_kernel()
{
    __shared__ float sctx[HDIM * HDIM];      // [d][e]
    __shared__ float seq[128 * HDIM];        // [row][d] normalized exp(q)

    const int bh = blockIdx.x;
    const int b  = bh >> 4;
    const int h  = bh & 15;
    const int tid  = threadIdx.x;
    const int warp = tid >> 5;
    const int lane = tid & 31;

    {
        const float4* src = reinterpret_cast<const float4*>(g_ctx + (size_t)bh * HDIM * HDIM);
        float4* dst = reinterpret_cast<float4*>(sctx);
        #pragma unroll
        for (int i = 0; i < 4; i++) dst[tid + i * 256] = src[tid + i * 256];
    }

    const int nbase = blockIdx.y * 128;
    const float* qbase = g_qkv + (size_t)b * SEQ * N_QKV + h * HDIM;
    #pragma unroll 1
    for (int i = 0; i < 16; i++) {
        int rloc = warp * 16 + i;
        const float* q = qbase + (size_t)(nbase + rloc) * N_QKV;
        float e0 = expf(q[lane]);
        float e1 = expf(q[lane + 32]);
        float rs = e0 + e1;
        #pragma unroll
        for (int s = 16; s > 0; s >>= 1) rs += __shfl_xor_sync(0xffffffffu, rs, s);
        float inv = 1.0f / rs;
        seq[rloc * HDIM + lane]      = e0 * inv;
        seq[rloc * HDIM + lane + 32] = e1 * inv;
    }
    __syncthreads();

    const int ty = tid >> 4;
    const int tx = tid & 15;
    const int r0 = ty * 8;
    const int e0 = tx * 4;

    float2 acc2[8][2];
    #pragma unroll
    for (int i = 0; i < 8; i++) {
        acc2[i][0] = make_float2(0.f, 0.f);
        acc2[i][1] = make_float2(0.f, 0.f);
    }

    #pragma unroll 4
    for (int d0 = 0; d0 < HDIM; d0 += 4) {
        float4 cv[4];
        #pragma unroll
        for (int k = 0; k < 4; k++)
            cv[k] = *reinterpret_cast<const float4*>(&sctx[(d0 + k) * HDIM + e0]);
        #pragma unroll
        for (int i = 0; i < 8; i++) {
            float4 ev = *reinterpret_cast<const float4*>(&seq[(r0 + i) * HDIM + d0]);
            float ea[4] = {ev.x, ev.y, ev.z, ev.w};
            #pragma unroll
            for (int k = 0; k < 4; k++) {
                float2 ed = make_float2(ea[k], ea[k]);
                acc2[i][0] = ffma2(ed, make_float2(cv[k].x, cv[k].y), acc2[i][0]);
                acc2[i][1] = ffma2(ed, make_float2(cv[k].z, cv[k].w), acc2[i][1]);
            }
        }
    }

    // fused split store into attn big/small halves
    const size_t obase = (size_t)(b * SEQ) * DIM + h * HDIM + e0;
    #pragma unroll
    for (int i = 0; i < 8; i++) {
        size_t o = obase + (size_t)(nbase + r0 + i) * DIM;
        uint32_t b01, s01, b23, s23;
        split2u(acc2[i][0].x, acc2[i][0].y, b01, s01);
        split2u(acc2[i][1].x, acc2[i][1].y, b23, s23);
        *reinterpret_cast<uint2*>(g_attnb + o) = make_uint2(b01, b23);
        *reinterpret_cast<uint2*>(g_attns + o) = make_uint2(s01, s23);
    }
}

// ---------------- launch ------------------------------------------------------
extern "C" void kernel_launch(void* const* d_in, const int* in_sizes, int n_in,
                              void* d_out, int out_size)
{
    const float* x      = (const float*)d_in[0];   // [4,4096,1024]
    const float* W_qkv  = (const float*)d_in[1];   // [1024,3072]
    const float* b_qkv  = (const float*)d_in[2];   // [3072]
    const float* W_proj = (const float*)d_in[3];   // [1024,1024]
    const float* b_proj = (const float*)d_in[4];   // [1024]
    float* out = (float*)d_out;                    // [4,4096,1024]

    float*  qkv;   cudaGetSymbolAddress((void**)&qkv,   g_qkv);
    __half* xb;    cudaGetSymbolAddress((void**)&xb,    g_xb);
    __half* xs;    cudaGetSymbolAddress((void**)&xs,    g_xs);
    __half* wqb;   cudaGetSymbolAddress((void**)&wqb,   g_wqkvb);
    __half* wqs;   cudaGetSymbolAddress((void**)&wqs,   g_wqkvs);
    __half* wpb;   cudaGetSymbolAddress((void**)&wpb,   g_wprjb);
    __half* wps;   cudaGetSymbolAddress((void**)&wps,   g_wprjs);
    __half* atb;   cudaGetSymbolAddress((void**)&atb,   g_attnb);
    __half* ats;   cudaGetSymbolAddress((void**)&ats,   g_attns);

    cudaFuncSetAttribute(gemm_f16x3_kernel,
                         cudaFuncAttributeMaxDynamicSharedMemorySize, GEMM_SMEM_BYTES);

    // 0) pre-split operands
    split_kernel<<<(ROWS * DIM / 4) / 256, 256>>>(x, xb, xs);
    split_wt_kernel<<<dim3(N_QKV / 32, DIM / 32), 256>>>(W_qkv, wqb, wqs, DIM, N_QKV);
    split_wt_kernel<<<dim3(DIM / 32, DIM / 32), 256>>>(W_proj, wpb, wps, DIM, DIM);

    // 1) qkv = x @ W_qkv + b_qkv
    {
        dim3 grid(N_QKV / 128, ROWS / 128);
        gemm_f16x3_kernel<<<grid, 256, GEMM_SMEM_BYTES>>>(xb, xs, wqb, wqs, b_qkv, qkv,
                                                          ROWS, N_QKV, DIM);
    }
    // 2) context partials over n-chunks
    context_partial_kernel<<<BATCH * HEADS * NCHUNK, 256>>>();
    // 3) reduce + normalize context
    reduce_ctx_kernel<<<BATCH * HEADS, 256>>>();
    // 4) attn = softmax_d(q) @ ctx  (writes split halves)
    {
        dim3 grid(BATCH * HEADS, SEQ / 128);
        qctx_kernel<<<grid, 256>>>();
    }
    // 5) out = attn @ W_proj + b_proj
    {
        dim3 grid(DIM / 128, ROWS / 128);
        gemm_f16x3_kernel<<<grid, 256, GEMM_SMEM_BYTES>>>(atb, ats, wpb, wps, b_proj, out,
                                                          ROWS, DIM, DIM);
    }
}

// round 17
// speedup vs baseline: 1.1260x; 1.1260x over previous
#include <cuda_runtime.h>
#include <cuda_fp16.h>
#include <cstdint>
#include <math.h>

// Problem dims (fixed by reference)
#define BATCH 4
#define SEQ   4096
#define DIM   1024
#define HEADS 16
#define HDIM  64            // DIM / HEADS
#define ROWS  (BATCH*SEQ)   // 16384
#define N_QKV (3*DIM)       // 3072
#define NCHUNK 8            // context split factor

// ---------------- scratch (device globals; no allocations allowed) ------------
__device__ float  g_qkv     [(size_t)ROWS * N_QKV];                // fp32 qkv
__device__ float  g_ctx     [(size_t)BATCH*HEADS*HDIM*HDIM];
__device__ float  g_ctxpart [(size_t)BATCH*HEADS*NCHUNK*HDIM*HDIM];
__device__ float  g_csumpart[(size_t)BATCH*HEADS*NCHUNK*HDIM];
// pre-split fp16 operands (big + small = exact-ish fp32)
__device__ __half g_xb   [(size_t)ROWS * DIM];     // x big     [M][K]
__device__ __half g_xs   [(size_t)ROWS * DIM];     // x small
__device__ __half g_wqkvb[(size_t)N_QKV * DIM];    // W_qkv^T big  [N][K]
__device__ __half g_wqkvs[(size_t)N_QKV * DIM];
__device__ __half g_wprjb[(size_t)DIM * DIM];      // W_proj^T big [N][K]
__device__ __half g_wprjs[(size_t)DIM * DIM];
__device__ __half g_attnb[(size_t)ROWS * DIM];     // attn big  [M][K]
__device__ __half g_attns[(size_t)ROWS * DIM];

// ---------------- helpers ----------------------------------------------------
__device__ __forceinline__ void mma_f16(float& c0, float& c1, float& c2, float& c3,
                                        uint32_t a0, uint32_t a1, uint32_t a2, uint32_t a3,
                                        uint32_t b0, uint32_t b1) {
    asm volatile(
        "mma.sync.aligned.m16n8k16.row.col.f32.f16.f16.f32 "
        "{%0,%1,%2,%3}, {%4,%5,%6,%7}, {%8,%9}, {%0,%1,%2,%3};\n"
        : "+f"(c0), "+f"(c1), "+f"(c2), "+f"(c3)
        : "r"(a0), "r"(a1), "r"(a2), "r"(a3), "r"(b0), "r"(b1));
}

__device__ __forceinline__ void cp_async16(uint32_t smem_addr, const void* gptr) {
    asm volatile("cp.async.cg.shared.global [%0], [%1], 16;\n"
                 :: "r"(smem_addr), "l"(gptr));
}
__device__ __forceinline__ void cp_commit() {
    asm volatile("cp.async.commit_group;\n" ::: "memory");
}
template <int N>
__device__ __forceinline__ void cp_wait() {
    asm volatile("cp.async.wait_group %0;\n" :: "n"(N) : "memory");
}

__device__ __forceinline__ float2 ffma2(float2 a, float2 b, float2 c) {
    uint64_t au, bu, cu, du;
    au = *reinterpret_cast<uint64_t*>(&a);
    bu = *reinterpret_cast<uint64_t*>(&b);
    cu = *reinterpret_cast<uint64_t*>(&c);
    asm("fma.rn.f32x2 %0, %1, %2, %3;" : "=l"(du) : "l"(au), "l"(bu), "l"(cu));
    return *reinterpret_cast<float2*>(&du);
}

// split pair of fp32 -> big half2 + small half2 (packed uint32)
__device__ __forceinline__ void split2u(float x, float y, uint32_t& big, uint32_t& sml) {
    __half2 hb = __floats2half2_rn(x, y);
    float2 back = __half22float2(hb);
    __half2 hs = __floats2half2_rn(x - back.x, y - back.y);
    big = *reinterpret_cast<uint32_t*>(&hb);
    sml = *reinterpret_cast<uint32_t*>(&hs);
}

// ---------------- prep: elementwise split of row-major fp32 -> half pairs -----
__global__ __launch_bounds__(256) void split_kernel(const float* __restrict__ src,
                                                    __half* __restrict__ ob,
                                                    __half* __restrict__ os)
{
    size_t t = (size_t)blockIdx.x * 256 + threadIdx.x;   // one float4 per thread
    float4 v = reinterpret_cast<const float4*>(src)[t];
    uint32_t b01, s01, b23, s23;
    split2u(v.x, v.y, b01, s01);
    split2u(v.z, v.w, b23, s23);
    uint2 ub = make_uint2(b01, b23);
    uint2 us = make_uint2(s01, s23);
    *reinterpret_cast<uint2*>(ob + 4 * t) = ub;
    *reinterpret_cast<uint2*>(os + 4 * t) = us;
}

// ---------------- prep: W [K][N] fp32 -> transposed [N][K] half pairs ---------
__global__ __launch_bounds__(256) void split_wt_kernel(const float* __restrict__ W,
                                                       __half* __restrict__ ob,
                                                       __half* __restrict__ os,
                                                       int K, int N)
{
    __shared__ float tile[32][33];
    const int n0 = blockIdx.x * 32;
    const int k0 = blockIdx.y * 32;
    const int tid = threadIdx.x;
    const int r  = tid >> 3;          // 0..31
    const int c4 = (tid & 7) * 4;     // 0..28

    float4 v = *reinterpret_cast<const float4*>(W + (size_t)(k0 + r) * N + n0 + c4);
    tile[r][c4] = v.x; tile[r][c4 + 1] = v.y; tile[r][c4 + 2] = v.z; tile[r][c4 + 3] = v.w;
    __syncthreads();

    // write transposed: thread -> n = r, k = c4..c4+3
    const int n = r;
    #pragma unroll
    for (int j = 0; j < 4; j++) {
        float f = tile[c4 + j][n];
        __half hb = __float2half_rn(f);
        __half hs = __float2half_rn(f - __half2float(hb));
        size_t o = (size_t)(n0 + n) * K + k0 + c4 + j;
        ob[o] = hb;
        os[o] = hs;
    }
}

// ---------------- big GEMM: C[M,N] = A[M,K] @ B^T[N,K] + bias  (3xFP16) -------
// A given as big/small half [M][K]; B given as big/small half [N][K] (pre-transposed).
// Block tile 128x128, BK=32, 8 warps 2(m)x4(n), warp tile 64x32, 2-stage cp.async.
// __launch_bounds__(256, 2): cap regs at 128 so 2 CTAs co-reside per SM
// (R6 ncu: occ=12.4%, tensor=49.8% at 1 CTA/SM; latency-bound, not tensor-bound).
// MMA issue is term-outer (bb over all tiles, then bs, then asml): per-accumulator
// accumulation order is unchanged (bitwise-identical) but RAW distance goes 1 -> 16.
#define ST_STRIDE 40                       // halfs per smem row (80B) -> conflict-free
#define ARR_HALFS (128 * ST_STRIDE)        // 5120 halfs per array
#define STAGE_HALFS (4 * ARR_HALFS)        // Ab, As, Bb, Bs
#define GEMM_SMEM_BYTES (2 * STAGE_HALFS * 2)   // 81920 B  (x2 CTAs = 160KB < 227KB)

__global__ __launch_bounds__(256, 2) void gemm_f16x3_kernel(
    const __half* __restrict__ Ab, const __half* __restrict__ As,
    const __half* __restrict__ Bb, const __half* __restrict__ Bs,
    const float* __restrict__ bias, float* __restrict__ C,
    int M, int N, int K)
{
    extern __shared__ __half smem[];

    const int tid  = threadIdx.x;
    const int warp = tid >> 5;
    const int lane = tid & 31;
    const int gid  = lane >> 2;     // 0..7
    const int tig  = lane & 3;      // 0..3

    const int m0 = blockIdx.y * 128;
    const int n0 = blockIdx.x * 128;
    const int wm = (warp & 1) * 64;
    const int wn = (warp >> 1) * 32;

    // per-thread cp.async slots: 2 chunks per array; chunk f covers row f>>2, halfs (f&3)*8
    int rr[2], cc[2];
    #pragma unroll
    for (int i = 0; i < 2; i++) {
        int f = tid + i * 256;
        rr[i] = f >> 2;
        cc[i] = (f & 3) * 8;
    }

    const int ntiles = K >> 5;

    auto issue_tile = [&](int kt, int s) {
        __half* Sab = smem + (size_t)s * STAGE_HALFS;
        __half* Sas = Sab + ARR_HALFS;
        __half* Sbb = Sas + ARR_HALFS;
        __half* Sbs = Sbb + ARR_HALFS;
        #pragma unroll
        for (int i = 0; i < 2; i++) {
            int r = rr[i], c = cc[i];
            size_t goA = (size_t)(m0 + r) * K + kt + c;
            size_t goB = (size_t)(n0 + r) * K + kt + c;
            cp_async16((uint32_t)__cvta_generic_to_shared(Sab + r * ST_STRIDE + c), Ab + goA);
            cp_async16((uint32_t)__cvta_generic_to_shared(Sas + r * ST_STRIDE + c), As + goA);
            cp_async16((uint32_t)__cvta_generic_to_shared(Sbb + r * ST_STRIDE + c), Bb + goB);
            cp_async16((uint32_t)__cvta_generic_to_shared(Sbs + r * ST_STRIDE + c), Bs + goB);
        }
        cp_commit();
    };

    float acc[4][4][4];
    #pragma unroll
    for (int i = 0; i < 4; i++)
        #pragma unroll
        for (int j = 0; j < 4; j++)
            #pragma unroll
            for (int r = 0; r < 4; r++) acc[i][j][r] = 0.f;

    issue_tile(0, 0);

    for (int t = 0; t < ntiles; t++) {
        const int s = t & 1;
        if (t + 1 < ntiles) {
            issue_tile((t + 1) << 5, s ^ 1);
            cp_wait<1>();
        } else {
            cp_wait<0>();
        }
        __syncthreads();

        const __half* Sab = smem + (size_t)s * STAGE_HALFS;
        const __half* Sas = Sab + ARR_HALFS;
        const __half* Sbb = Sas + ARR_HALFS;
        const __half* Sbs = Sbb + ARR_HALFS;
        // uint32 views (all frag offsets are even halfs)
        const uint32_t* uab = reinterpret_cast<const uint32_t*>(Sab);
        const uint32_t* uas = reinterpret_cast<const uint32_t*>(Sas);
        const uint32_t* ubb = reinterpret_cast<const uint32_t*>(Sbb);
        const uint32_t* ubs = reinterpret_cast<const uint32_t*>(Sbs);

        #pragma unroll
        for (int kk = 0; kk < 32; kk += 16) {
            const int k0w = (kk + 2 * tig) >> 1;        // uint32 col index
            uint32_t ab[4][4], asml[4][4];
            #pragma unroll
            for (int mt = 0; mt < 4; mt++) {
                int rA = wm + mt * 16 + gid;
                int base0 = rA * (ST_STRIDE / 2) + k0w;
                int base1 = (rA + 8) * (ST_STRIDE / 2) + k0w;
                ab[mt][0] = uab[base0];     ab[mt][1] = uab[base1];
                ab[mt][2] = uab[base0 + 4]; ab[mt][3] = uab[base1 + 4];
                asml[mt][0] = uas[base0];     asml[mt][1] = uas[base1];
                asml[mt][2] = uas[base0 + 4]; asml[mt][3] = uas[base1 + 4];
            }
            uint32_t bb[4][2], bs[4][2];
            #pragma unroll
            for (int nt = 0; nt < 4; nt++) {
                int cB = wn + nt * 8 + gid;
                int base = cB * (ST_STRIDE / 2) + k0w;
                bb[nt][0] = ubb[base]; bb[nt][1] = ubb[base + 4];
                bs[nt][0] = ubs[base]; bs[nt][1] = ubs[base + 4];
            }
            // term 1: Ab * Bb   (16 independent MMAs)
            #pragma unroll
            for (int mt = 0; mt < 4; mt++)
                #pragma unroll
                for (int nt = 0; nt < 4; nt++)
                    mma_f16(acc[mt][nt][0], acc[mt][nt][1], acc[mt][nt][2], acc[mt][nt][3],
                            ab[mt][0], ab[mt][1], ab[mt][2], ab[mt][3],
                            bb[nt][0], bb[nt][1]);
            // term 2: Ab * Bs
            #pragma unroll
            for (int mt = 0; mt < 4; mt++)
                #pragma unroll
                for (int nt = 0; nt < 4; nt++)
                    mma_f16(acc[mt][nt][0], acc[mt][nt][1], acc[mt][nt][2], acc[mt][nt][3],
                            ab[mt][0], ab[mt][1], ab[mt][2], ab[mt][3],
                            bs[nt][0], bs[nt][1]);
            // term 3: As * Bb
            #pragma unroll
            for (int mt = 0; mt < 4; mt++)
                #pragma unroll
                for (int nt = 0; nt < 4; nt++)
                    mma_f16(acc[mt][nt][0], acc[mt][nt][1], acc[mt][nt][2], acc[mt][nt][3],
                            asml[mt][0], asml[mt][1], asml[mt][2], asml[mt][3],
                            bb[nt][0], bb[nt][1]);
        }
        __syncthreads();
    }

    // ---- epilogue: + bias, store ----
    #pragma unroll
    for (int mt = 0; mt < 4; mt++) {
        int row = m0 + wm + mt * 16 + gid;
        #pragma unroll
        for (int nt = 0; nt < 4; nt++) {
            int col = n0 + wn + nt * 8 + tig * 2;
            float b0 = bias[col], b1 = bias[col + 1];
            C[(size_t)row * N + col]           = acc[mt][nt][0] + b0;
            C[(size_t)row * N + col + 1]       = acc[mt][nt][1] + b1;
            C[(size_t)(row + 8) * N + col]     = acc[mt][nt][2] + b0;
            C[(size_t)(row + 8) * N + col + 1] = acc[mt][nt][3] + b1;
        }
    }
}

// ---------------- context partial: per (b,h,chunk) ----------------------------
#define CK_STRIDE 68
#define CHUNK_ROWS (SEQ / NCHUNK)   // 512
__global__ __launch_bounds__(256) void context_partial_kernel()
{
    __shared__ float sk[64 * CK_STRIDE];
    __shared__ float sv[64 * CK_STRIDE];

    const int bid = blockIdx.x;
    const int bh  = bid >> 3;
    const int c   = bid & 7;
    const int b   = bh >> 4;
    const int h   = bh & 15;
    const int tid = threadIdx.x;
    const int ty  = tid >> 4;
    const int tx  = tid & 15;
    const int d0  = ty * 4;
    const int e0  = tx * 4;

    const float* kbase = g_qkv + (size_t)b * SEQ * N_QKV + DIM     + h * HDIM;
    const float* vbase = g_qkv + (size_t)b * SEQ * N_QKV + 2 * DIM + h * HDIM;

    float2 acc2[4][2];
    #pragma unroll
    for (int i = 0; i < 4; i++) {
        acc2[i][0] = make_float2(0.f, 0.f);
        acc2[i][1] = make_float2(0.f, 0.f);
    }
    float csum = 0.f;

    const int nlo = c * CHUNK_ROWS;
    for (int n0 = nlo; n0 < nlo + CHUNK_ROWS; n0 += 64) {
        #pragma unroll
        for (int i = 0; i < 4; i++) {
            int f  = tid + i * 256;
            int r  = f >> 4;
            int c4 = (f & 15) * 4;
            size_t go = (size_t)(n0 + r) * N_QKV + c4;
            float4 kv = *reinterpret_cast<const float4*>(kbase + go);
            float* dk = &sk[r * CK_STRIDE + c4];
            dk[0] = expf(kv.x); dk[1] = expf(kv.y); dk[2] = expf(kv.z); dk[3] = expf(kv.w);
            float4 vv = *reinterpret_cast<const float4*>(vbase + go);
            *reinterpret_cast<float4*>(&sv[r * CK_STRIDE + c4]) = vv;
        }
        __syncthreads();

        if (tid < 64) {
            #pragma unroll 8
            for (int r = 0; r < 64; r++) csum += sk[r * CK_STRIDE + tid];
        }
        #pragma unroll 4
        for (int r = 0; r < 64; r++) {
            float4 kf = *reinterpret_cast<const float4*>(&sk[r * CK_STRIDE + d0]);
            float4 vf = *reinterpret_cast<const float4*>(&sv[r * CK_STRIDE + e0]);
            float2 v0 = make_float2(vf.x, vf.y);
            float2 v1 = make_float2(vf.z, vf.w);
            float ka[4] = {kf.x, kf.y, kf.z, kf.w};
            #pragma unroll
            for (int i = 0; i < 4; i++) {
                float2 kd = make_float2(ka[i], ka[i]);
                acc2[i][0] = ffma2(kd, v0, acc2[i][0]);
                acc2[i][1] = ffma2(kd, v1, acc2[i][1]);
            }
        }
        __syncthreads();
    }

    float* part = g_ctxpart + (size_t)bid * HDIM * HDIM;
    #pragma unroll
    for (int i = 0; i < 4; i++) {
        part[(d0 + i) * HDIM + e0    ] = acc2[i][0].x;
        part[(d0 + i) * HDIM + e0 + 1] = acc2[i][0].y;
        part[(d0 + i) * HDIM + e0 + 2] = acc2[i][1].x;
        part[(d0 + i) * HDIM + e0 + 3] = acc2[i][1].y;
    }
    if (tid < 64) g_csumpart[(size_t)bid * HDIM + tid] = csum;
}

// ---------------- reduce partials -> normalized ctx ---------------------------
__global__ __launch_bounds__(256) void reduce_ctx_kernel()
{
    __shared__ float sinv[64];
    const int bh  = blockIdx.x;
    const int tid = threadIdx.x;

    if (tid < 64) {
        float s = 0.f;
        #pragma unroll
        for (int c = 0; c < NCHUNK; c++)
            s += g_csumpart[(size_t)(bh * NCHUNK + c) * HDIM + tid];
        sinv[tid] = 1.0f / s;
    }
    __syncthreads();

    for (int idx = tid; idx < HDIM * HDIM; idx += 256) {
        float s = 0.f;
        #pragma unroll
        for (int c = 0; c < NCHUNK; c++)
            s += g_ctxpart[(size_t)(bh * NCHUNK + c) * HDIM * HDIM + idx];
        g_ctx[(size_t)bh * HDIM * HDIM + idx] = s * sinv[idx >> 6];
    }
}

// ---------------- q-softmax + q @ ctx, fused fp16-split store -----------------
__global__ __launch_bounds__(256) void qctx_kernel()
{
    __shared__ float sctx[HDIM * HDIM];      // [d][e]
    __shared__ float seq[128 * HDIM];        // [row][d] normalized exp(q)

    const int bh = blockIdx.x;
    const int b  = bh >> 4;
    const int h  = bh & 15;
    const int tid  = threadIdx.x;
    const int warp = tid >> 5;
    const int lane = tid & 31;

    {
        const float4* src = reinterpret_cast<const float4*>(g_ctx + (size_t)bh * HDIM * HDIM);
        float4* dst = reinterpret_cast<float4*>(sctx);
        #pragma unroll
        for (int i = 0; i < 4; i++) dst[tid + i * 256] = src[tid + i * 256];
    }

    const int nbase = blockIdx.y * 128;
    const float* qbase = g_qkv + (size_t)b * SEQ * N_QKV + h * HDIM;
    #pragma unroll 1
    for (int i = 0; i < 16; i++) {
        int rloc = warp * 16 + i;
        const float* q = qbase + (size_t)(nbase + rloc) * N_QKV;
        float e0 = expf(q[lane]);
        float e1 = expf(q[lane + 32]);
        float rs = e0 + e1;
        #pragma unroll
        for (int s = 16; s > 0; s >>= 1) rs += __shfl_xor_sync(0xffffffffu, rs, s);
        float inv = 1.0f / rs;
        seq[rloc * HDIM + lane]      = e0 * inv;
        seq[rloc * HDIM + lane + 32] = e1 * inv;
    }
    __syncthreads();

    const int ty = tid >> 4;
    const int tx = tid & 15;
    const int r0 = ty * 8;
    const int e0 = tx * 4;

    float2 acc2[8][2];
    #pragma unroll
    for (int i = 0; i < 8; i++) {
        acc2[i][0] = make_float2(0.f, 0.f);
        acc2[i][1] = make_float2(0.f, 0.f);
    }

    #pragma unroll 4
    for (int d0 = 0; d0 < HDIM; d0 += 4) {
        float4 cv[4];
        #pragma unroll
        for (int k = 0; k < 4; k++)
            cv[k] = *reinterpret_cast<const float4*>(&sctx[(d0 + k) * HDIM + e0]);
        #pragma unroll
        for (int i = 0; i < 8; i++) {
            float4 ev = *reinterpret_cast<const float4*>(&seq[(r0 + i) * HDIM + d0]);
            float ea[4] = {ev.x, ev.y, ev.z, ev.w};
            #pragma unroll
            for (int k = 0; k < 4; k++) {
                float2 ed = make_float2(ea[k], ea[k]);
                acc2[i][0] = ffma2(ed, make_float2(cv[k].x, cv[k].y), acc2[i][0]);
                acc2[i][1] = ffma2(ed, make_float2(cv[k].z, cv[k].w), acc2[i][1]);
            }
        }
    }

    // fused split store into attn big/small halves
    const size_t obase = (size_t)(b * SEQ) * DIM + h * HDIM + e0;
    #pragma unroll
    for (int i = 0; i < 8; i++) {
        size_t o = obase + (size_t)(nbase + r0 + i) * DIM;
        uint32_t b01, s01, b23, s23;
        split2u(acc2[i][0].x, acc2[i][0].y, b01, s01);
        split2u(acc2[i][1].x, acc2[i][1].y, b23, s23);
        *reinterpret_cast<uint2*>(g_attnb + o) = make_uint2(b01, b23);
        *reinterpret_cast<uint2*>(g_attns + o) = make_uint2(s01, s23);
    }
}

// ---------------- launch ------------------------------------------------------
extern "C" void kernel_launch(void* const* d_in, const int* in_sizes, int n_in,
                              void* d_out, int out_size)
{
    const float* x      = (const float*)d_in[0];   // [4,4096,1024]
    const float* W_qkv  = (const float*)d_in[1];   // [1024,3072]
    const float* b_qkv  = (const float*)d_in[2];   // [3072]
    const float* W_proj = (const float*)d_in[3];   // [1024,1024]
    const float* b_proj = (const float*)d_in[4];   // [1024]
    float* out = (float*)d_out;                    // [4,4096,1024]

    float*  qkv;   cudaGetSymbolAddress((void**)&qkv,   g_qkv);
    __half* xb;    cudaGetSymbolAddress((void**)&xb,    g_xb);
    __half* xs;    cudaGetSymbolAddress((void**)&xs,    g_xs);
    __half* wqb;   cudaGetSymbolAddress((void**)&wqb,   g_wqkvb);
    __half* wqs;   cudaGetSymbolAddress((void**)&wqs,   g_wqkvs);
    __half* wpb;   cudaGetSymbolAddress((void**)&wpb,   g_wprjb);
    __half* wps;   cudaGetSymbolAddress((void**)&wps,   g_wprjs);
    __half* atb;   cudaGetSymbolAddress((void**)&atb,   g_attnb);
    __half* ats;   cudaGetSymbolAddress((void**)&ats,   g_attns);

    cudaFuncSetAttribute(gemm_f16x3_kernel,
                         cudaFuncAttributeMaxDynamicSharedMemorySize, GEMM_SMEM_BYTES);

    // 0) pre-split operands
    split_kernel<<<(ROWS * DIM / 4) / 256, 256>>>(x, xb, xs);
    split_wt_kernel<<<dim3(N_QKV / 32, DIM / 32), 256>>>(W_qkv, wqb, wqs, DIM, N_QKV);
    split_wt_kernel<<<dim3(DIM / 32, DIM / 32), 256>>>(W_proj, wpb, wps, DIM, DIM);

    // 1) qkv = x @ W_qkv + b_qkv
    {
        dim3 grid(N_QKV / 128, ROWS / 128);
        gemm_f16x3_kernel<<<grid, 256, GEMM_SMEM_BYTES>>>(xb, xs, wqb, wqs, b_qkv, qkv,
                                                          ROWS, N_QKV, DIM);
    }
    // 2) context partials over n-chunks
    context_partial_kernel<<<BATCH * HEADS * NCHUNK, 256>>>();
    // 3) reduce + normalize context
    reduce_ctx_kernel<<<BATCH * HEADS, 256>>>();
    // 4) attn = softmax_d(q) @ ctx  (writes split halves)
    {
        dim3 grid(BATCH * HEADS, SEQ / 128);
        qctx_kernel<<<grid, 256>>>();
    }
    // 5) out = attn @ W_proj + b_proj
    {
        dim3 grid(DIM / 128, ROWS / 128);
        gemm_f16x3_kernel<<<grid, 256, GEMM_SMEM_BYTES>>>(atb, ats, wpb, wps, b_proj, out,
                                                          ROWS, DIM, DIM);
    }
}